// round 15
// baseline (speedup 1.0000x reference)
#include <cuda_runtime.h>
#include <cuda_fp16.h>
#include <math.h>
#include <stdint.h>

// ---------------- problem constants ----------------
#define N_TOKENS 2048
#define HIDDEN   2880
#define N_HEADS  64
#define N_KV     8
#define HEAD_DIM 64
#define QKV_DIM  5120          // (64 + 2*8) * 64
#define Q_SZ     4096          // 64*64
#define KV_SZ    512           // 8*64
#define WINDOW   128
#define SM_SCALE 0.125f

// ---------------- scratch (static device globals; no allocation) ----------------
__device__ __half g_tnorm_h[N_TOKENS * HIDDEN];   // A for QKV GEMM (fp16)
__device__ __half g_qkv_h  [N_TOKENS * QKV_DIM];  // QKV output, post-RoPE (fp16)
__device__ __half g_attn_h [N_TOKENS * Q_SZ];     // A for O GEMM (fp16)
__device__ __half g_wqkv16 [HIDDEN * QKV_DIM];    // w_qkv fp16, native [K=2880][N=5120]
__device__ __half g_wo16   [Q_SZ * HIDDEN];       // w_o  fp16, native [K=4096][N=2880]
__device__ float  g_cos    [N_TOKENS * 32];
__device__ float  g_sin    [N_TOKENS * 32];
__device__ double g_invf   [32];
__device__ double g_conc;

// ---------------- helpers ----------------
__device__ __forceinline__ uint32_t smem_u32(const void* p) {
    uint32_t a;
    asm("{ .reg .u64 t; cvta.to.shared.u64 t, %1; cvt.u32.u64 %0, t; }" : "=r"(a) : "l"(p));
    return a;
}
__device__ __forceinline__ void cp_async16(uint32_t dst, const void* src, int sz) {
    asm volatile("cp.async.cg.shared.global [%0], [%1], 16, %2;"
                 :: "r"(dst), "l"(src), "r"(sz) : "memory");
}
#define CP_COMMIT() asm volatile("cp.async.commit_group;" ::: "memory")
#define CP_WAITG(n) asm volatile("cp.async.wait_group %0;" :: "n"(n) : "memory")

__device__ __forceinline__ void mma_f16(float* c, const uint32_t* a, const uint32_t* b) {
    asm volatile("mma.sync.aligned.m16n8k16.row.col.f32.f16.f16.f32 "
                 "{%0,%1,%2,%3}, {%4,%5,%6,%7}, {%8,%9}, {%0,%1,%2,%3};"
                 : "+f"(c[0]), "+f"(c[1]), "+f"(c[2]), "+f"(c[3])
                 : "r"(a[0]), "r"(a[1]), "r"(a[2]), "r"(a[3]), "r"(b[0]), "r"(b[1]));
}
__device__ __forceinline__ void ldsm4(uint32_t& r0, uint32_t& r1, uint32_t& r2, uint32_t& r3,
                                      uint32_t addr) {
    asm volatile("ldmatrix.sync.aligned.m8n8.x4.shared.b16 {%0,%1,%2,%3}, [%4];"
                 : "=r"(r0), "=r"(r1), "=r"(r2), "=r"(r3) : "r"(addr));
}
__device__ __forceinline__ void ldsm4t(uint32_t& r0, uint32_t& r1, uint32_t& r2, uint32_t& r3,
                                       uint32_t addr) {
    asm volatile("ldmatrix.sync.aligned.m8n8.x4.trans.shared.b16 {%0,%1,%2,%3}, [%4];"
                 : "=r"(r0), "=r"(r1), "=r"(r2), "=r"(r3) : "r"(addr));
}
__device__ __forceinline__ uint32_t packh2(float a, float b) {
    __half2 h = __floats2half2_rn(a, b);
    return *(uint32_t*)&h;
}

// ---------------- RoPE inverse frequencies (fp64, tiny kernel) ----------------
__global__ void rope_invf_kernel() {
    int i = threadIdx.x;           // 0..31
    double di = (double)i;
    double lnbase = log(150000.0);
    double freq = exp((2.0 * di / 64.0) * lnbase);
    double twopi = 6.283185307179586476925286766559;
    double low  = 32.0 * log(4096.0 / (32.0 * twopi)) / lnbase;
    double high = 32.0 * log(4096.0 / (1.0  * twopi)) / lnbase;
    double interp = 1.0 / (32.0 * freq);
    double extrap = 1.0 / freq;
    double ramp = (di - low) / (high - low);
    double clipped = ramp < 0.0 ? 0.0 : (ramp > 1.0 ? 1.0 : ramp);
    double m = 1.0 - clipped;
    g_invf[i] = interp * (1.0 - m) + extrap * m;
    if (i == 0) g_conc = 0.1 * log(32.0) + 1.0;
}

// ---------------- RoPE tables: double phase + reduction, fp32 sincos ----------------
__global__ void rope_table_kernel() {
    int idx = blockIdx.x * 256 + threadIdx.x;   // 65536 entries
    int t = idx >> 5, i = idx & 31;
    double f = (double)t * g_invf[i];
    double q = rint(f * 0.159154943091895335768883763373);   // 1/(2*pi)
    double r = f - q * 6.283185307179586476925286766559;     // |r| <= pi
    float rf = (float)r;
    float s, c;
    sincosf(rf, &s, &c);
    float conc = (float)g_conc;
    g_cos[idx] = c * conc;
    g_sin[idx] = s * conc;
}

// ---------------- RMSNorm (vectorized single pass, writes fp16) ----------------
__global__ void rmsnorm_kernel(const float* __restrict__ x,
                               const float* __restrict__ scale) {
    int t = blockIdx.x;
    int tid = threadIdx.x;                 // 256 threads; 720 float4 per row
    const float4* row4 = (const float4*)(x + (size_t)t * HIDDEN);
    float4 v4[3];
    float s = 0.f;
    #pragma unroll
    for (int k = 0; k < 3; k++) {
        int i4 = tid + k * 256;
        if (i4 < 720) {
            float4 v = row4[i4];
            v4[k] = v;
            s += v.x * v.x + v.y * v.y + v.z * v.z + v.w * v.w;
        }
    }
    __shared__ float red[8];
    __shared__ float s_r;
    #pragma unroll
    for (int o = 16; o; o >>= 1) s += __shfl_xor_sync(0xffffffffu, s, o);
    if ((tid & 31) == 0) red[tid >> 5] = s;
    __syncthreads();
    if (tid == 0) {
        float tot = 0.f;
        #pragma unroll
        for (int w = 0; w < 8; w++) tot += red[w];
        s_r = rsqrtf(tot / (float)HIDDEN + 1e-5f);
    }
    __syncthreads();
    float r = s_r;
    __half* out = g_tnorm_h + (size_t)t * HIDDEN;
    const float4* sc4 = (const float4*)scale;
    #pragma unroll
    for (int k = 0; k < 3; k++) {
        int i4 = tid + k * 256;
        if (i4 < 720) {
            float4 sv = sc4[i4];
            float4 v = v4[k];
            __half2 h0 = __floats2half2_rn(v.x * r * sv.x, v.y * r * sv.y);
            __half2 h1 = __floats2half2_rn(v.z * r * sv.z, v.w * r * sv.w);
            uint2 pack;
            pack.x = *(uint32_t*)&h0;
            pack.y = *(uint32_t*)&h1;
            *(uint2*)(out + i4 * 4) = pack;
        }
    }
}

// ---------------- streaming convert f32 -> f16 (same layout) ----------------
__global__ void convert_h_kernel(const float* __restrict__ src, __half* __restrict__ dst) {
    size_t i = ((size_t)blockIdx.x * 256 + threadIdx.x) * 4;
    float4 v = *(const float4*)(src + i);
    __half2 h0 = __floats2half2_rn(v.x, v.y);
    __half2 h1 = __floats2half2_rn(v.z, v.w);
    uint2 pack;
    pack.x = *(uint32_t*)&h0;
    pack.y = *(uint32_t*)&h1;
    *(uint2*)(dst + i) = pack;
}

// ---------------- fp16 mma.sync GEMM ----------------
// CTA tile 128x128, 8 warps (4x2), warp tile 32x64, K-chunk 64, 3-stage cp.async,
// 2 CTAs/SM. B loaded from NATIVE [K][N] weights via ldmatrix.trans.
// Loads hoisted BEFORE the MMA block; chunk loop unrolled by 3 (static stages).
// MODE 0: QKV epilogue (bias + fused RoPE + fp16 store). MODE 1: fp32 + bias + resid.
#define GK    64
#define ROWH  72                               // A row pitch (halves)
#define BROW  136                               // B row pitch (halves)
#define A_STAGE_HALFS (128 * ROWH)             // 9216
#define B_STAGE_HALFS (GK * BROW)              // 8704
#define STAGE_BYTES ((A_STAGE_HALFS + B_STAGE_HALFS) * 2)   // 35840
#define GEMM_SMEM   (3 * STAGE_BYTES)                       // 107520

__device__ __forceinline__ void gemm_load_chunk(const __half* __restrict__ A,
                                                const __half* __restrict__ B,
                                                uint32_t sbase, int m0, int n0,
                                                int N, int K, int ci, int stage_idx,
                                                int tid) {
    int k0 = ci * GK;
    uint32_t stage = sbase + stage_idx * STAGE_BYTES;
    uint32_t bstage = stage + A_STAGE_HALFS * 2;
    #pragma unroll
    for (int s = 0; s < 8; s++) {
        int seg = tid + s * 256;              // 0..2047
        if (seg < 1024) {                     // A: 128 rows x 8 16B-segs
            int row = seg >> 3, c = seg & 7;
            cp_async16(stage + row * (ROWH * 2) + c * 16,
                       A + (size_t)(m0 + row) * K + k0 + c * 8, 16);
        } else {                              // B: 64 K-rows x 16 16B-segs (N-contig)
            int s2 = seg - 1024;
            int row = s2 >> 4, c = s2 & 15;
            int col = n0 + c * 8;
            int valid = col < N;
            cp_async16(bstage + row * (BROW * 2) + c * 16,
                       B + (size_t)(k0 + row) * N + (valid ? col : 0), valid ? 16 : 0);
        }
    }
}

template <int MODE>
__global__ __launch_bounds__(256, 2)
void mma_gemm_kernel(const __half* __restrict__ A, const __half* __restrict__ B,
                     const float* __restrict__ bias, const float* __restrict__ resid,
                     float* __restrict__ C, int N, int K) {
    extern __shared__ char smem[];
    uint32_t sbase = smem_u32(smem);
    int tid = threadIdx.x;
    int warp = tid >> 5, lane = tid & 31;
    int lr = lane >> 2, lc = lane & 3;
    int wm = (warp >> 1) * 32;                // 0,32,64,96
    int wn = (warp & 1) * 64;                 // 0,64
    int m0 = blockIdx.y * 128;
    int n0 = blockIdx.x * 128;

    int lr8 = lane & 7;
    uint32_t a_off = ((uint32_t)(wm + ((lane >> 3) & 1) * 8 + lr8) * ROWH
                      + (lane >> 4) * 8) * 2;
    uint32_t b_off = ((uint32_t)(((lane >> 3) & 1) * 8 + lr8) * BROW
                      + (lane >> 4) * 8 + wn) * 2;

    float c[2][8][4];
    #pragma unroll
    for (int im = 0; im < 2; im++)
        #pragma unroll
        for (int in_ = 0; in_ < 8; in_++)
            #pragma unroll
            for (int r = 0; r < 4; r++) c[im][in_][r] = 0.f;

    const int nchunks = K / GK;
    gemm_load_chunk(A, B, sbase, m0, n0, N, K, 0, 0, tid); CP_COMMIT();
    gemm_load_chunk(A, B, sbase, m0, n0, N, K, 1, 1, tid); CP_COMMIT();

    #pragma unroll 3
    for (int i = 0; i < nchunks; i++) {
        int st = i % 3;
        CP_WAITG(1);
        __syncthreads();
        // hoisted prefetch: stage (i+2)%3 == (i-1)%3 is free after this barrier
        if (i + 2 < nchunks)
            gemm_load_chunk(A, B, sbase, m0, n0, N, K, i + 2, (i + 2) % 3, tid);
        CP_COMMIT();
        uint32_t stage = sbase + st * STAGE_BYTES;
        uint32_t astage = stage + a_off;
        uint32_t bstage = stage + A_STAGE_HALFS * 2 + b_off;
        #pragma unroll
        for (int ks = 0; ks < 4; ks++) {
            uint32_t af[2][4], bf[4][4];
            #pragma unroll
            for (int im = 0; im < 2; im++)
                ldsm4(af[im][0], af[im][1], af[im][2], af[im][3],
                      astage + im * (16 * ROWH * 2) + ks * 16 * 2);
            #pragma unroll
            for (int n2 = 0; n2 < 4; n2++)
                ldsm4t(bf[n2][0], bf[n2][1], bf[n2][2], bf[n2][3],
                       bstage + ks * (16 * BROW * 2) + n2 * 16 * 2);
            #pragma unroll
            for (int im = 0; im < 2; im++)
                #pragma unroll
                for (int in_ = 0; in_ < 8; in_++)
                    mma_f16(c[im][in_], af[im], &bf[in_ >> 1][(in_ & 1) * 2]);
        }
    }

    if (MODE == 0) {
        int h = (n0 + wn) >> 6;
        #pragma unroll
        for (int im = 0; im < 2; im++) {
            int gr = m0 + wm + im * 16 + lr;
            int gr2 = gr + 8;
            float v[8][4];
            #pragma unroll
            for (int in_ = 0; in_ < 8; in_++) {
                int gc = n0 + wn + in_ * 8 + lc * 2;
                float2 bv = *(const float2*)(bias + gc);
                v[in_][0] = c[im][in_][0] + bv.x;
                v[in_][1] = c[im][in_][1] + bv.y;
                v[in_][2] = c[im][in_][2] + bv.x;
                v[in_][3] = c[im][in_][3] + bv.y;
            }
            if (h < 72) {  // q + k heads get RoPE
                #pragma unroll
                for (int in_ = 0; in_ < 4; in_++) {
                    int d = in_ * 8 + lc * 2;
                    float cA0 = g_cos[gr * 32 + d],  sA0 = g_sin[gr * 32 + d];
                    float cA1 = g_cos[gr * 32 + d + 1], sA1 = g_sin[gr * 32 + d + 1];
                    float cB0 = g_cos[gr2 * 32 + d], sB0 = g_sin[gr2 * 32 + d];
                    float cB1 = g_cos[gr2 * 32 + d + 1], sB1 = g_sin[gr2 * 32 + d + 1];
                    float x1, x2;
                    x1 = v[in_][0]; x2 = v[in_ + 4][0];
                    v[in_][0] = x1 * cA0 - x2 * sA0; v[in_ + 4][0] = x2 * cA0 + x1 * sA0;
                    x1 = v[in_][1]; x2 = v[in_ + 4][1];
                    v[in_][1] = x1 * cA1 - x2 * sA1; v[in_ + 4][1] = x2 * cA1 + x1 * sA1;
                    x1 = v[in_][2]; x2 = v[in_ + 4][2];
                    v[in_][2] = x1 * cB0 - x2 * sB0; v[in_ + 4][2] = x2 * cB0 + x1 * sB0;
                    x1 = v[in_][3]; x2 = v[in_ + 4][3];
                    v[in_][3] = x1 * cB1 - x2 * sB1; v[in_ + 4][3] = x2 * cB1 + x1 * sB1;
                }
            }
            #pragma unroll
            for (int in_ = 0; in_ < 8; in_++) {
                int gc = n0 + wn + in_ * 8 + lc * 2;
                __half2 h0 = __floats2half2_rn(v[in_][0], v[in_][1]);
                __half2 h1 = __floats2half2_rn(v[in_][2], v[in_][3]);
                *(__half2*)(g_qkv_h + (size_t)gr * QKV_DIM + gc) = h0;
                *(__half2*)(g_qkv_h + (size_t)gr2 * QKV_DIM + gc) = h1;
            }
        }
    } else {
        #pragma unroll
        for (int im = 0; im < 2; im++) {
            int gr = m0 + wm + im * 16 + lr;
            #pragma unroll
            for (int in_ = 0; in_ < 8; in_++) {
                int gc = n0 + wn + in_ * 8 + lc * 2;
                if (gc < N) {
                    float2 bv = *(const float2*)(bias + gc);
                    float2 v0 = make_float2(c[im][in_][0] + bv.x, c[im][in_][1] + bv.y);
                    float2 v1 = make_float2(c[im][in_][2] + bv.x, c[im][in_][3] + bv.y);
                    float2 r0 = *(const float2*)(resid + (size_t)gr * N + gc);
                    float2 r1 = *(const float2*)(resid + (size_t)(gr + 8) * N + gc);
                    v0.x += r0.x; v0.y += r0.y;
                    v1.x += r1.x; v1.y += r1.y;
                    *(float2*)(C + (size_t)gr * N + gc) = v0;
                    *(float2*)(C + (size_t)(gr + 8) * N + gc) = v1;
                }
            }
        }
    }
}

// ---------------- flash-style mma attention (fp16 inputs) ----------------
// TQ=8 tokens/block, 128 threads (4 warps), 3 CTAs/SM.
#define TQ    8
#define KMAX  144
#define AROW  72
#define ATTN_SMEM ((64 + KMAX + KMAX) * AROW * 2)   // 50688 B

__global__ __launch_bounds__(128, 3)
void attn_mma_kernel(const float* __restrict__ sink) {
    extern __shared__ __half hsm[];
    __half* Qs = hsm;                    // [64][72]
    __half* Ks = Qs + 64 * AROW;         // [144][72]
    __half* Vs = Ks + KMAX * AROW;       // [144][72]

    int q0 = blockIdx.x * TQ;
    int kv = blockIdx.y;
    int tid = threadIdx.x;
    int warp = tid >> 5, lane = tid & 31;
    int lr = lane >> 2, lc = lane & 3;

    int kstart = q0 - WINDOW; if (kstart < 0) kstart = 0;
    int kcnt = q0 + TQ - kstart;          // <= 136

    for (int seg = tid; seg < 64 * 8; seg += 128) {
        int row = seg >> 3, d = (seg & 7) * 8;
        int t = q0 + (row >> 3), g = row & 7;
        *(uint4*)(Qs + row * AROW + d) =
            *(const uint4*)(g_qkv_h + (size_t)t * QKV_DIM + (kv * 8 + g) * 64 + d);
    }
    for (int seg = tid; seg < KMAX * 8; seg += 128) {
        int j = seg >> 3, d = (seg & 7) * 8;
        if (j < kcnt) {
            const __half* row = g_qkv_h + (size_t)(kstart + j) * QKV_DIM;
            *(uint4*)(Ks + j * AROW + d) = *(const uint4*)(row + Q_SZ + kv * 64 + d);
            *(uint4*)(Vs + j * AROW + d) = *(const uint4*)(row + Q_SZ + KV_SZ + kv * 64 + d);
        } else {
            uint4 z = make_uint4(0, 0, 0, 0);
            *(uint4*)(Ks + j * AROW + d) = z;
            *(uint4*)(Vs + j * AROW + d) = z;
        }
    }
    __syncthreads();

    int lr8 = lane & 7;
    uint32_t qbase = smem_u32(Qs)
        + ((uint32_t)(16 * warp + ((lane >> 3) & 1) * 8 + lr8) * AROW + (lane >> 4) * 8) * 2;
    uint32_t kbase = smem_u32(Ks)
        + ((uint32_t)((lane >> 4) * 8 + lr8) * AROW + ((lane >> 3) & 1) * 8) * 2;
    uint32_t vbase = smem_u32(Vs)
        + ((uint32_t)(((lane >> 3) & 1) * 8 + lr8) * AROW + (lane >> 4) * 8) * 2;

    float sc[18][4];
    #pragma unroll
    for (int j = 0; j < 18; j++)
        #pragma unroll
        for (int e = 0; e < 4; e++) sc[j][e] = 0.f;

    #pragma unroll
    for (int kb = 0; kb < 4; kb++) {
        uint32_t koff = kb * 16 * 2;
        uint32_t af[4];
        ldsm4(af[0], af[1], af[2], af[3], qbase + koff);
        #pragma unroll
        for (int j2 = 0; j2 < 9; j2++) {
            uint32_t bf[4];
            ldsm4(bf[0], bf[1], bf[2], bf[3], kbase + j2 * (16 * AROW * 2) + koff);
            mma_f16(sc[2 * j2],     af, &bf[0]);
            mma_f16(sc[2 * j2 + 1], af, &bf[2]);
        }
    }

    int t0 = q0 + 2 * warp;
    int t1 = t0 + 1;
    float snk = sink[kv * 8 + lr];
    float m0 = snk, m1 = snk;
    #pragma unroll
    for (int j = 0; j < 18; j++) {
        int colb = j * 8 + lc * 2;
        #pragma unroll
        for (int e = 0; e < 4; e++) {
            int ktok = kstart + colb + (e & 1);
            int trow = (e < 2) ? t0 : t1;
            bool valid = (ktok <= trow) && (trow - ktok <= WINDOW);
            float v = valid ? sc[j][e] * SM_SCALE : -1e30f;
            sc[j][e] = v;
            if (e < 2) m0 = fmaxf(m0, v); else m1 = fmaxf(m1, v);
        }
    }
    m0 = fmaxf(m0, __shfl_xor_sync(0xffffffffu, m0, 1));
    m0 = fmaxf(m0, __shfl_xor_sync(0xffffffffu, m0, 2));
    m1 = fmaxf(m1, __shfl_xor_sync(0xffffffffu, m1, 1));
    m1 = fmaxf(m1, __shfl_xor_sync(0xffffffffu, m1, 2));

    float s0 = 0.f, s1 = 0.f;
    #pragma unroll
    for (int j = 0; j < 18; j++) {
        float p0 = __expf(sc[j][0] - m0);
        float p1 = __expf(sc[j][1] - m0);
        float p2 = __expf(sc[j][2] - m1);
        float p3 = __expf(sc[j][3] - m1);
        sc[j][0] = p0; sc[j][1] = p1; sc[j][2] = p2; sc[j][3] = p3;
        s0 += p0 + p1; s1 += p2 + p3;
    }
    s0 += __shfl_xor_sync(0xffffffffu, s0, 1);
    s0 += __shfl_xor_sync(0xffffffffu, s0, 2);
    s1 += __shfl_xor_sync(0xffffffffu, s1, 1);
    s1 += __shfl_xor_sync(0xffffffffu, s1, 2);
    float inv0 = 1.f / (s0 + __expf(snk - m0));
    float inv1 = 1.f / (s1 + __expf(snk - m1));

    float co[8][4];
    #pragma unroll
    for (int na = 0; na < 8; na++)
        #pragma unroll
        for (int e = 0; e < 4; e++) co[na][e] = 0.f;

    #pragma unroll
    for (int kc = 0; kc < 9; kc++) {
        uint32_t a[4];
        a[0] = packh2(sc[2 * kc][0],     sc[2 * kc][1]);
        a[1] = packh2(sc[2 * kc][2],     sc[2 * kc][3]);
        a[2] = packh2(sc[2 * kc + 1][0], sc[2 * kc + 1][1]);
        a[3] = packh2(sc[2 * kc + 1][2], sc[2 * kc + 1][3]);
        #pragma unroll
        for (int n2 = 0; n2 < 4; n2++) {
            uint32_t bf[4];
            ldsm4t(bf[0], bf[1], bf[2], bf[3],
                   vbase + kc * (16 * AROW * 2) + n2 * 16 * 2);
            mma_f16(co[2 * n2],     a, &bf[0]);
            mma_f16(co[2 * n2 + 1], a, &bf[2]);
        }
    }

    int hh = kv * 8 + lr;
    #pragma unroll
    for (int na = 0; na < 8; na++) {
        int col = hh * 64 + na * 8 + lc * 2;
        __half2 v0 = __floats2half2_rn(co[na][0] * inv0, co[na][1] * inv0);
        __half2 v1 = __floats2half2_rn(co[na][2] * inv1, co[na][3] * inv1);
        *(__half2*)(g_attn_h + (size_t)t0 * Q_SZ + col) = v0;
        *(__half2*)(g_attn_h + (size_t)t1 * Q_SZ + col) = v1;
    }
}

// ---------------- launch ----------------
extern "C" void kernel_launch(void* const* d_in, const int* in_sizes, int n_in,
                              void* d_out, int out_size) {
    const float* x      = (const float*)d_in[0];
    const float* scale  = (const float*)d_in[1];
    const float* sink   = (const float*)d_in[2];
    const float* w_qkv  = (const float*)d_in[3];
    const float* b_qkv  = (const float*)d_in[4];
    const float* w_o    = (const float*)d_in[5];
    const float* b_o    = (const float*)d_in[6];
    float* out = (float*)d_out;

    __half *tnorm, *attnb, *wqkv16, *wo16;
    cudaGetSymbolAddress((void**)&tnorm,  g_tnorm_h);
    cudaGetSymbolAddress((void**)&attnb,  g_attn_h);
    cudaGetSymbolAddress((void**)&wqkv16, g_wqkv16);
    cudaGetSymbolAddress((void**)&wo16,   g_wo16);

    static int init_done = 0;
    static cudaStream_t s_cvt, s_rope;
    static cudaEvent_t ev_fork, ev_wqkv, ev_wo, ev_rope;
    if (!init_done) {
        cudaFuncSetAttribute(attn_mma_kernel, cudaFuncAttributeMaxDynamicSharedMemorySize,
                             ATTN_SMEM);
        cudaFuncSetAttribute(mma_gemm_kernel<0>, cudaFuncAttributeMaxDynamicSharedMemorySize,
                             GEMM_SMEM);
        cudaFuncSetAttribute(mma_gemm_kernel<1>, cudaFuncAttributeMaxDynamicSharedMemorySize,
                             GEMM_SMEM);
        cudaStreamCreateWithFlags(&s_cvt,  cudaStreamNonBlocking);
        cudaStreamCreateWithFlags(&s_rope, cudaStreamNonBlocking);
        cudaEventCreateWithFlags(&ev_fork, cudaEventDisableTiming);
        cudaEventCreateWithFlags(&ev_wqkv, cudaEventDisableTiming);
        cudaEventCreateWithFlags(&ev_wo,   cudaEventDisableTiming);
        cudaEventCreateWithFlags(&ev_rope, cudaEventDisableTiming);
        init_done = 1;
    }

    // fork
    cudaEventRecord(ev_fork, 0);
    cudaStreamWaitEvent(s_cvt,  ev_fork, 0);
    cudaStreamWaitEvent(s_rope, ev_fork, 0);

    // convert stream: weight fp16 conversions
    convert_h_kernel<<<(HIDDEN * QKV_DIM) / 1024, 256, 0, s_cvt>>>(w_qkv, wqkv16);
    cudaEventRecord(ev_wqkv, s_cvt);
    convert_h_kernel<<<(Q_SZ * HIDDEN) / 1024, 256, 0, s_cvt>>>(w_o, wo16);
    cudaEventRecord(ev_wo, s_cvt);

    // rope stream: tables (needed only by QKV epilogue)
    rope_invf_kernel<<<1, 32, 0, s_rope>>>();
    rope_table_kernel<<<(N_TOKENS * 32) / 256, 256, 0, s_rope>>>();
    cudaEventRecord(ev_rope, s_rope);

    // main stream: rmsnorm (the true QKV-GEMM dependency)
    rmsnorm_kernel<<<N_TOKENS, 256>>>(x, scale);

    // join w_qkv + rope, then QKV GEMM with fused RoPE epilogue -> g_qkv_h (fp16)
    cudaStreamWaitEvent(0, ev_wqkv, 0);
    cudaStreamWaitEvent(0, ev_rope, 0);
    {
        dim3 grid(QKV_DIM / 128, N_TOKENS / 128);     // (40, 16) = 640 CTAs, 2/SM
        mma_gemm_kernel<0><<<grid, 256, GEMM_SMEM>>>(tnorm, wqkv16, b_qkv, nullptr, nullptr,
                                                     QKV_DIM, HIDDEN);
    }

    // flash-style mma attention with sink (TQ=8, 3 CTAs/SM)
    {
        dim3 grid(N_TOKENS / TQ, N_KV);               // (256, 8) = 2048 CTAs
        attn_mma_kernel<<<grid, 128, ATTN_SMEM>>>(sink);
    }

    // join w_o convert, then O GEMM + bias + residual
    cudaStreamWaitEvent(0, ev_wo, 0);
    {
        dim3 grid((HIDDEN + 127) / 128, N_TOKENS / 128);  // (23, 16) = 368 CTAs, 2/SM
        mma_gemm_kernel<1><<<grid, 256, GEMM_SMEM>>>(attnb, wo16, b_o, x, out,
                                                     HIDDEN, Q_SZ);
    }
}

// round 16
// speedup vs baseline: 1.0833x; 1.0833x over previous
#include <cuda_runtime.h>
#include <cuda_fp16.h>
#include <math.h>
#include <stdint.h>

// ---------------- problem constants ----------------
#define N_TOKENS 2048
#define HIDDEN   2880
#define N_HEADS  64
#define N_KV     8
#define HEAD_DIM 64
#define QKV_DIM  5120          // (64 + 2*8) * 64
#define Q_SZ     4096          // 64*64
#define KV_SZ    512           // 8*64
#define WINDOW   128
#define SM_SCALE 0.125f

// ---------------- scratch (static device globals; no allocation) ----------------
__device__ __half g_tnorm_h[N_TOKENS * HIDDEN];   // A for QKV GEMM (fp16)
__device__ __half g_qkv_h  [N_TOKENS * QKV_DIM];  // QKV output, post-RoPE (fp16)
__device__ __half g_attn_h [N_TOKENS * Q_SZ];     // A for O GEMM (fp16)
__device__ __half g_wqkv16 [HIDDEN * QKV_DIM];    // w_qkv fp16, native [K=2880][N=5120]
__device__ __half g_wo16   [Q_SZ * HIDDEN];       // w_o  fp16, native [K=4096][N=2880]
__device__ float  g_cos    [N_TOKENS * 32];
__device__ float  g_sin    [N_TOKENS * 32];
__device__ double g_invf   [32];
__device__ double g_conc;

// ---------------- helpers ----------------
__device__ __forceinline__ uint32_t smem_u32(const void* p) {
    uint32_t a;
    asm("{ .reg .u64 t; cvta.to.shared.u64 t, %1; cvt.u32.u64 %0, t; }" : "=r"(a) : "l"(p));
    return a;
}
__device__ __forceinline__ void cp_async16(uint32_t dst, const void* src, int sz) {
    asm volatile("cp.async.cg.shared.global [%0], [%1], 16, %2;"
                 :: "r"(dst), "l"(src), "r"(sz) : "memory");
}
#define CP_COMMIT() asm volatile("cp.async.commit_group;" ::: "memory")
#define CP_WAITG(n) asm volatile("cp.async.wait_group %0;" :: "n"(n) : "memory")

__device__ __forceinline__ void mma_f16(float* c, const uint32_t* a, const uint32_t* b) {
    asm volatile("mma.sync.aligned.m16n8k16.row.col.f32.f16.f16.f32 "
                 "{%0,%1,%2,%3}, {%4,%5,%6,%7}, {%8,%9}, {%0,%1,%2,%3};"
                 : "+f"(c[0]), "+f"(c[1]), "+f"(c[2]), "+f"(c[3])
                 : "r"(a[0]), "r"(a[1]), "r"(a[2]), "r"(a[3]), "r"(b[0]), "r"(b[1]));
}
__device__ __forceinline__ void ldsm4(uint32_t& r0, uint32_t& r1, uint32_t& r2, uint32_t& r3,
                                      uint32_t addr) {
    asm volatile("ldmatrix.sync.aligned.m8n8.x4.shared.b16 {%0,%1,%2,%3}, [%4];"
                 : "=r"(r0), "=r"(r1), "=r"(r2), "=r"(r3) : "r"(addr));
}
__device__ __forceinline__ void ldsm4t(uint32_t& r0, uint32_t& r1, uint32_t& r2, uint32_t& r3,
                                       uint32_t addr) {
    asm volatile("ldmatrix.sync.aligned.m8n8.x4.trans.shared.b16 {%0,%1,%2,%3}, [%4];"
                 : "=r"(r0), "=r"(r1), "=r"(r2), "=r"(r3) : "r"(addr));
}
__device__ __forceinline__ uint32_t packh2(float a, float b) {
    __half2 h = __floats2half2_rn(a, b);
    return *(uint32_t*)&h;
}

// ---------------- RoPE inverse frequencies (fp64, tiny kernel) ----------------
__global__ void rope_invf_kernel() {
    int i = threadIdx.x;           // 0..31
    double di = (double)i;
    double lnbase = log(150000.0);
    double freq = exp((2.0 * di / 64.0) * lnbase);
    double twopi = 6.283185307179586476925286766559;
    double low  = 32.0 * log(4096.0 / (32.0 * twopi)) / lnbase;
    double high = 32.0 * log(4096.0 / (1.0  * twopi)) / lnbase;
    double interp = 1.0 / (32.0 * freq);
    double extrap = 1.0 / freq;
    double ramp = (di - low) / (high - low);
    double clipped = ramp < 0.0 ? 0.0 : (ramp > 1.0 ? 1.0 : ramp);
    double m = 1.0 - clipped;
    g_invf[i] = interp * (1.0 - m) + extrap * m;
    if (i == 0) g_conc = 0.1 * log(32.0) + 1.0;
}

// ---------------- RoPE tables: double phase + reduction, fp32 sincos ----------------
__global__ void rope_table_kernel() {
    int idx = blockIdx.x * 256 + threadIdx.x;   // 65536 entries
    int t = idx >> 5, i = idx & 31;
    double f = (double)t * g_invf[i];
    double q = rint(f * 0.159154943091895335768883763373);   // 1/(2*pi)
    double r = f - q * 6.283185307179586476925286766559;     // |r| <= pi
    float rf = (float)r;
    float s, c;
    sincosf(rf, &s, &c);
    float conc = (float)g_conc;
    g_cos[idx] = c * conc;
    g_sin[idx] = s * conc;
}

// ---------------- RMSNorm (vectorized single pass, writes fp16) ----------------
__global__ void rmsnorm_kernel(const float* __restrict__ x,
                               const float* __restrict__ scale) {
    int t = blockIdx.x;
    int tid = threadIdx.x;                 // 256 threads; 720 float4 per row
    const float4* row4 = (const float4*)(x + (size_t)t * HIDDEN);
    float4 v4[3];
    float s = 0.f;
    #pragma unroll
    for (int k = 0; k < 3; k++) {
        int i4 = tid + k * 256;
        if (i4 < 720) {
            float4 v = row4[i4];
            v4[k] = v;
            s += v.x * v.x + v.y * v.y + v.z * v.z + v.w * v.w;
        }
    }
    __shared__ float red[8];
    __shared__ float s_r;
    #pragma unroll
    for (int o = 16; o; o >>= 1) s += __shfl_xor_sync(0xffffffffu, s, o);
    if ((tid & 31) == 0) red[tid >> 5] = s;
    __syncthreads();
    if (tid == 0) {
        float tot = 0.f;
        #pragma unroll
        for (int w = 0; w < 8; w++) tot += red[w];
        s_r = rsqrtf(tot / (float)HIDDEN + 1e-5f);
    }
    __syncthreads();
    float r = s_r;
    __half* out = g_tnorm_h + (size_t)t * HIDDEN;
    const float4* sc4 = (const float4*)scale;
    #pragma unroll
    for (int k = 0; k < 3; k++) {
        int i4 = tid + k * 256;
        if (i4 < 720) {
            float4 sv = sc4[i4];
            float4 v = v4[k];
            __half2 h0 = __floats2half2_rn(v.x * r * sv.x, v.y * r * sv.y);
            __half2 h1 = __floats2half2_rn(v.z * r * sv.z, v.w * r * sv.w);
            uint2 pack;
            pack.x = *(uint32_t*)&h0;
            pack.y = *(uint32_t*)&h1;
            *(uint2*)(out + i4 * 4) = pack;
        }
    }
}

// ---------------- streaming convert f32 -> f16 (same layout) ----------------
__global__ void convert_h_kernel(const float* __restrict__ src, __half* __restrict__ dst) {
    size_t i = ((size_t)blockIdx.x * 256 + threadIdx.x) * 4;
    float4 v = *(const float4*)(src + i);
    __half2 h0 = __floats2half2_rn(v.x, v.y);
    __half2 h1 = __floats2half2_rn(v.z, v.w);
    uint2 pack;
    pack.x = *(uint32_t*)&h0;
    pack.y = *(uint32_t*)&h1;
    *(uint2*)(dst + i) = pack;
}

// ---------------- fp16 mma.sync GEMM (R14-exact mainloop) ----------------
// CTA tile 128x128, 8 warps (4x2), warp tile 32x64, K-chunk 64, 3-stage cp.async,
// 2 CTAs/SM. B loaded from NATIVE [K][N] weights via ldmatrix.trans.
// MODE 0: QKV epilogue (bias + fused RoPE + fp16 store). MODE 1: fp32 + bias + resid.
#define GK    64
#define ROWH  72                               // A row pitch (halves)
#define BROW  136                              // B row pitch (halves): 128 data + 8 pad
#define A_STAGE_HALFS (128 * ROWH)             // 9216
#define B_STAGE_HALFS (GK * BROW)              // 8704
#define STAGE_BYTES ((A_STAGE_HALFS + B_STAGE_HALFS) * 2)   // 35840
#define GEMM_SMEM   (3 * STAGE_BYTES)                       // 107520

__device__ __forceinline__ void gemm_load_chunk(const __half* __restrict__ A,
                                                const __half* __restrict__ B,
                                                uint32_t sbase, int m0, int n0,
                                                int N, int K, int ci, int tid) {
    int k0 = ci * GK;
    uint32_t stage = sbase + (ci % 3) * STAGE_BYTES;
    uint32_t bstage = stage + A_STAGE_HALFS * 2;
    #pragma unroll
    for (int s = 0; s < 8; s++) {
        int seg = tid + s * 256;              // 0..2047
        if (seg < 1024) {                     // A: 128 rows x 8 16B-segs
            int row = seg >> 3, c = seg & 7;
            cp_async16(stage + row * (ROWH * 2) + c * 16,
                       A + (size_t)(m0 + row) * K + k0 + c * 8, 16);
        } else {                              // B: 64 K-rows x 16 16B-segs (N-contig)
            int s2 = seg - 1024;
            int row = s2 >> 4, c = s2 & 15;
            int col = n0 + c * 8;
            int valid = col < N;
            cp_async16(bstage + row * (BROW * 2) + c * 16,
                       B + (size_t)(k0 + row) * N + (valid ? col : 0), valid ? 16 : 0);
        }
    }
}

template <int MODE>
__global__ __launch_bounds__(256, 2)
void mma_gemm_kernel(const __half* __restrict__ A, const __half* __restrict__ B,
                     const float* __restrict__ bias, const float* __restrict__ resid,
                     float* __restrict__ C, int N, int K) {
    extern __shared__ char smem[];
    uint32_t sbase = smem_u32(smem);
    int tid = threadIdx.x;
    int warp = tid >> 5, lane = tid & 31;
    int lr = lane >> 2, lc = lane & 3;
    int wm = (warp >> 1) * 32;                // 0,32,64,96
    int wn = (warp & 1) * 64;                 // 0,64
    int m0 = blockIdx.y * 128;
    int n0 = blockIdx.x * 128;

    int lr8 = lane & 7;
    uint32_t a_off = ((uint32_t)(wm + ((lane >> 3) & 1) * 8 + lr8) * ROWH
                      + (lane >> 4) * 8) * 2;
    uint32_t b_off = ((uint32_t)(((lane >> 3) & 1) * 8 + lr8) * BROW
                      + (lane >> 4) * 8 + wn) * 2;

    float c[2][8][4];
    #pragma unroll
    for (int im = 0; im < 2; im++)
        #pragma unroll
        for (int in_ = 0; in_ < 8; in_++)
            #pragma unroll
            for (int r = 0; r < 4; r++) c[im][in_][r] = 0.f;

    const int nchunks = K / GK;
    gemm_load_chunk(A, B, sbase, m0, n0, N, K, 0, tid); CP_COMMIT();
    gemm_load_chunk(A, B, sbase, m0, n0, N, K, 1, tid); CP_COMMIT();

    for (int i = 0; i < nchunks; i++) {
        CP_WAITG(1);
        __syncthreads();
        uint32_t stage = sbase + (i % 3) * STAGE_BYTES;
        uint32_t astage = stage + a_off;
        uint32_t bstage = stage + A_STAGE_HALFS * 2 + b_off;
        #pragma unroll
        for (int ks = 0; ks < 4; ks++) {
            uint32_t af[2][4], bf[4][4];
            #pragma unroll
            for (int im = 0; im < 2; im++)
                ldsm4(af[im][0], af[im][1], af[im][2], af[im][3],
                      astage + im * (16 * ROWH * 2) + ks * 16 * 2);
            #pragma unroll
            for (int n2 = 0; n2 < 4; n2++)
                ldsm4t(bf[n2][0], bf[n2][1], bf[n2][2], bf[n2][3],
                       bstage + ks * (16 * BROW * 2) + n2 * 16 * 2);
            #pragma unroll
            for (int im = 0; im < 2; im++)
                #pragma unroll
                for (int in_ = 0; in_ < 8; in_++)
                    mma_f16(c[im][in_], af[im], &bf[in_ >> 1][(in_ & 1) * 2]);
        }
        if (i + 2 < nchunks) gemm_load_chunk(A, B, sbase, m0, n0, N, K, i + 2, tid);
        CP_COMMIT();
    }

    if (MODE == 0) {
        int h = (n0 + wn) >> 6;
        #pragma unroll
        for (int im = 0; im < 2; im++) {
            int gr = m0 + wm + im * 16 + lr;
            int gr2 = gr + 8;
            float v[8][4];
            #pragma unroll
            for (int in_ = 0; in_ < 8; in_++) {
                int gc = n0 + wn + in_ * 8 + lc * 2;
                float2 bv = *(const float2*)(bias + gc);
                v[in_][0] = c[im][in_][0] + bv.x;
                v[in_][1] = c[im][in_][1] + bv.y;
                v[in_][2] = c[im][in_][2] + bv.x;
                v[in_][3] = c[im][in_][3] + bv.y;
            }
            if (h < 72) {  // q + k heads get RoPE
                #pragma unroll
                for (int in_ = 0; in_ < 4; in_++) {
                    int d = in_ * 8 + lc * 2;
                    float cA0 = g_cos[gr * 32 + d],  sA0 = g_sin[gr * 32 + d];
                    float cA1 = g_cos[gr * 32 + d + 1], sA1 = g_sin[gr * 32 + d + 1];
                    float cB0 = g_cos[gr2 * 32 + d], sB0 = g_sin[gr2 * 32 + d];
                    float cB1 = g_cos[gr2 * 32 + d + 1], sB1 = g_sin[gr2 * 32 + d + 1];
                    float x1, x2;
                    x1 = v[in_][0]; x2 = v[in_ + 4][0];
                    v[in_][0] = x1 * cA0 - x2 * sA0; v[in_ + 4][0] = x2 * cA0 + x1 * sA0;
                    x1 = v[in_][1]; x2 = v[in_ + 4][1];
                    v[in_][1] = x1 * cA1 - x2 * sA1; v[in_ + 4][1] = x2 * cA1 + x1 * sA1;
                    x1 = v[in_][2]; x2 = v[in_ + 4][2];
                    v[in_][2] = x1 * cB0 - x2 * sB0; v[in_ + 4][2] = x2 * cB0 + x1 * sB0;
                    x1 = v[in_][3]; x2 = v[in_ + 4][3];
                    v[in_][3] = x1 * cB1 - x2 * sB1; v[in_ + 4][3] = x2 * cB1 + x1 * sB1;
                }
            }
            #pragma unroll
            for (int in_ = 0; in_ < 8; in_++) {
                int gc = n0 + wn + in_ * 8 + lc * 2;
                __half2 h0 = __floats2half2_rn(v[in_][0], v[in_][1]);
                __half2 h1 = __floats2half2_rn(v[in_][2], v[in_][3]);
                *(__half2*)(g_qkv_h + (size_t)gr * QKV_DIM + gc) = h0;
                *(__half2*)(g_qkv_h + (size_t)gr2 * QKV_DIM + gc) = h1;
            }
        }
    } else {
        #pragma unroll
        for (int im = 0; im < 2; im++) {
            int gr = m0 + wm + im * 16 + lr;
            #pragma unroll
            for (int in_ = 0; in_ < 8; in_++) {
                int gc = n0 + wn + in_ * 8 + lc * 2;
                if (gc < N) {
                    float2 bv = *(const float2*)(bias + gc);
                    float2 v0 = make_float2(c[im][in_][0] + bv.x, c[im][in_][1] + bv.y);
                    float2 v1 = make_float2(c[im][in_][2] + bv.x, c[im][in_][3] + bv.y);
                    float2 r0 = *(const float2*)(resid + (size_t)gr * N + gc);
                    float2 r1 = *(const float2*)(resid + (size_t)(gr + 8) * N + gc);
                    v0.x += r0.x; v0.y += r0.y;
                    v1.x += r1.x; v1.y += r1.y;
                    *(float2*)(C + (size_t)gr * N + gc) = v0;
                    *(float2*)(C + (size_t)(gr + 8) * N + gc) = v1;
                }
            }
        }
    }
}

// ---------------- flash-style mma attention (fp16 inputs) ----------------
// TQ=8 tokens/block, 128 threads (4 warps), 3 CTAs/SM.
#define TQ    8
#define KMAX  144
#define AROW  72
#define ATTN_SMEM ((64 + KMAX + KMAX) * AROW * 2)   // 50688 B

__global__ __launch_bounds__(128, 3)
void attn_mma_kernel(const float* __restrict__ sink) {
    extern __shared__ __half hsm[];
    __half* Qs = hsm;                    // [64][72]
    __half* Ks = Qs + 64 * AROW;         // [144][72]
    __half* Vs = Ks + KMAX * AROW;       // [144][72]

    int q0 = blockIdx.x * TQ;
    int kv = blockIdx.y;
    int tid = threadIdx.x;
    int warp = tid >> 5, lane = tid & 31;
    int lr = lane >> 2, lc = lane & 3;

    int kstart = q0 - WINDOW; if (kstart < 0) kstart = 0;
    int kcnt = q0 + TQ - kstart;          // <= 136

    for (int seg = tid; seg < 64 * 8; seg += 128) {
        int row = seg >> 3, d = (seg & 7) * 8;
        int t = q0 + (row >> 3), g = row & 7;
        *(uint4*)(Qs + row * AROW + d) =
            *(const uint4*)(g_qkv_h + (size_t)t * QKV_DIM + (kv * 8 + g) * 64 + d);
    }
    for (int seg = tid; seg < KMAX * 8; seg += 128) {
        int j = seg >> 3, d = (seg & 7) * 8;
        if (j < kcnt) {
            const __half* row = g_qkv_h + (size_t)(kstart + j) * QKV_DIM;
            *(uint4*)(Ks + j * AROW + d) = *(const uint4*)(row + Q_SZ + kv * 64 + d);
            *(uint4*)(Vs + j * AROW + d) = *(const uint4*)(row + Q_SZ + KV_SZ + kv * 64 + d);
        } else {
            uint4 z = make_uint4(0, 0, 0, 0);
            *(uint4*)(Ks + j * AROW + d) = z;
            *(uint4*)(Vs + j * AROW + d) = z;
        }
    }
    __syncthreads();

    int lr8 = lane & 7;
    uint32_t qbase = smem_u32(Qs)
        + ((uint32_t)(16 * warp + ((lane >> 3) & 1) * 8 + lr8) * AROW + (lane >> 4) * 8) * 2;
    uint32_t kbase = smem_u32(Ks)
        + ((uint32_t)((lane >> 4) * 8 + lr8) * AROW + ((lane >> 3) & 1) * 8) * 2;
    uint32_t vbase = smem_u32(Vs)
        + ((uint32_t)(((lane >> 3) & 1) * 8 + lr8) * AROW + (lane >> 4) * 8) * 2;

    float sc[18][4];
    #pragma unroll
    for (int j = 0; j < 18; j++)
        #pragma unroll
        for (int e = 0; e < 4; e++) sc[j][e] = 0.f;

    #pragma unroll
    for (int kb = 0; kb < 4; kb++) {
        uint32_t koff = kb * 16 * 2;
        uint32_t af[4];
        ldsm4(af[0], af[1], af[2], af[3], qbase + koff);
        #pragma unroll
        for (int j2 = 0; j2 < 9; j2++) {
            uint32_t bf[4];
            ldsm4(bf[0], bf[1], bf[2], bf[3], kbase + j2 * (16 * AROW * 2) + koff);
            mma_f16(sc[2 * j2],     af, &bf[0]);
            mma_f16(sc[2 * j2 + 1], af, &bf[2]);
        }
    }

    int t0 = q0 + 2 * warp;
    int t1 = t0 + 1;
    float snk = sink[kv * 8 + lr];
    float m0 = snk, m1 = snk;
    #pragma unroll
    for (int j = 0; j < 18; j++) {
        int colb = j * 8 + lc * 2;
        #pragma unroll
        for (int e = 0; e < 4; e++) {
            int ktok = kstart + colb + (e & 1);
            int trow = (e < 2) ? t0 : t1;
            bool valid = (ktok <= trow) && (trow - ktok <= WINDOW);
            float v = valid ? sc[j][e] * SM_SCALE : -1e30f;
            sc[j][e] = v;
            if (e < 2) m0 = fmaxf(m0, v); else m1 = fmaxf(m1, v);
        }
    }
    m0 = fmaxf(m0, __shfl_xor_sync(0xffffffffu, m0, 1));
    m0 = fmaxf(m0, __shfl_xor_sync(0xffffffffu, m0, 2));
    m1 = fmaxf(m1, __shfl_xor_sync(0xffffffffu, m1, 1));
    m1 = fmaxf(m1, __shfl_xor_sync(0xffffffffu, m1, 2));

    float s0 = 0.f, s1 = 0.f;
    #pragma unroll
    for (int j = 0; j < 18; j++) {
        float p0 = __expf(sc[j][0] - m0);
        float p1 = __expf(sc[j][1] - m0);
        float p2 = __expf(sc[j][2] - m1);
        float p3 = __expf(sc[j][3] - m1);
        sc[j][0] = p0; sc[j][1] = p1; sc[j][2] = p2; sc[j][3] = p3;
        s0 += p0 + p1; s1 += p2 + p3;
    }
    s0 += __shfl_xor_sync(0xffffffffu, s0, 1);
    s0 += __shfl_xor_sync(0xffffffffu, s0, 2);
    s1 += __shfl_xor_sync(0xffffffffu, s1, 1);
    s1 += __shfl_xor_sync(0xffffffffu, s1, 2);
    float inv0 = 1.f / (s0 + __expf(snk - m0));
    float inv1 = 1.f / (s1 + __expf(snk - m1));

    float co[8][4];
    #pragma unroll
    for (int na = 0; na < 8; na++)
        #pragma unroll
        for (int e = 0; e < 4; e++) co[na][e] = 0.f;

    #pragma unroll
    for (int kc = 0; kc < 9; kc++) {
        uint32_t a[4];
        a[0] = packh2(sc[2 * kc][0],     sc[2 * kc][1]);
        a[1] = packh2(sc[2 * kc][2],     sc[2 * kc][3]);
        a[2] = packh2(sc[2 * kc + 1][0], sc[2 * kc + 1][1]);
        a[3] = packh2(sc[2 * kc + 1][2], sc[2 * kc + 1][3]);
        #pragma unroll
        for (int n2 = 0; n2 < 4; n2++) {
            uint32_t bf[4];
            ldsm4t(bf[0], bf[1], bf[2], bf[3],
                   vbase + kc * (16 * AROW * 2) + n2 * 16 * 2);
            mma_f16(co[2 * n2],     a, &bf[0]);
            mma_f16(co[2 * n2 + 1], a, &bf[2]);
        }
    }

    int hh = kv * 8 + lr;
    #pragma unroll
    for (int na = 0; na < 8; na++) {
        int col = hh * 64 + na * 8 + lc * 2;
        __half2 v0 = __floats2half2_rn(co[na][0] * inv0, co[na][1] * inv0);
        __half2 v1 = __floats2half2_rn(co[na][2] * inv1, co[na][3] * inv1);
        *(__half2*)(g_attn_h + (size_t)t0 * Q_SZ + col) = v0;
        *(__half2*)(g_attn_h + (size_t)t1 * Q_SZ + col) = v1;
    }
}

// ---------------- launch ----------------
extern "C" void kernel_launch(void* const* d_in, const int* in_sizes, int n_in,
                              void* d_out, int out_size) {
    const float* x      = (const float*)d_in[0];
    const float* scale  = (const float*)d_in[1];
    const float* sink   = (const float*)d_in[2];
    const float* w_qkv  = (const float*)d_in[3];
    const float* b_qkv  = (const float*)d_in[4];
    const float* w_o    = (const float*)d_in[5];
    const float* b_o    = (const float*)d_in[6];
    float* out = (float*)d_out;

    __half *tnorm, *attnb, *wqkv16, *wo16;
    cudaGetSymbolAddress((void**)&tnorm,  g_tnorm_h);
    cudaGetSymbolAddress((void**)&attnb,  g_attn_h);
    cudaGetSymbolAddress((void**)&wqkv16, g_wqkv16);
    cudaGetSymbolAddress((void**)&wo16,   g_wo16);

    static int init_done = 0;
    static cudaStream_t s_cvt, s_rope;
    static cudaEvent_t ev_fork, ev_wqkv, ev_wo, ev_rope;
    if (!init_done) {
        cudaFuncSetAttribute(attn_mma_kernel, cudaFuncAttributeMaxDynamicSharedMemorySize,
                             ATTN_SMEM);
        cudaFuncSetAttribute(mma_gemm_kernel<0>, cudaFuncAttributeMaxDynamicSharedMemorySize,
                             GEMM_SMEM);
        cudaFuncSetAttribute(mma_gemm_kernel<1>, cudaFuncAttributeMaxDynamicSharedMemorySize,
                             GEMM_SMEM);
        cudaStreamCreateWithFlags(&s_cvt,  cudaStreamNonBlocking);
        cudaStreamCreateWithFlags(&s_rope, cudaStreamNonBlocking);
        cudaEventCreateWithFlags(&ev_fork, cudaEventDisableTiming);
        cudaEventCreateWithFlags(&ev_wqkv, cudaEventDisableTiming);
        cudaEventCreateWithFlags(&ev_wo,   cudaEventDisableTiming);
        cudaEventCreateWithFlags(&ev_rope, cudaEventDisableTiming);
        init_done = 1;
    }

    // fork
    cudaEventRecord(ev_fork, 0);
    cudaStreamWaitEvent(s_cvt,  ev_fork, 0);
    cudaStreamWaitEvent(s_rope, ev_fork, 0);

    // convert stream: weight fp16 conversions
    convert_h_kernel<<<(HIDDEN * QKV_DIM) / 1024, 256, 0, s_cvt>>>(w_qkv, wqkv16);
    cudaEventRecord(ev_wqkv, s_cvt);
    convert_h_kernel<<<(Q_SZ * HIDDEN) / 1024, 256, 0, s_cvt>>>(w_o, wo16);
    cudaEventRecord(ev_wo, s_cvt);

    // rope stream: tables (needed only by QKV epilogue)
    rope_invf_kernel<<<1, 32, 0, s_rope>>>();
    rope_table_kernel<<<(N_TOKENS * 32) / 256, 256, 0, s_rope>>>();
    cudaEventRecord(ev_rope, s_rope);

    // main stream: rmsnorm (the true QKV-GEMM dependency)
    rmsnorm_kernel<<<N_TOKENS, 256>>>(x, scale);

    // join w_qkv + rope, then QKV GEMM with fused RoPE epilogue -> g_qkv_h (fp16)
    cudaStreamWaitEvent(0, ev_wqkv, 0);
    cudaStreamWaitEvent(0, ev_rope, 0);
    {
        dim3 grid(QKV_DIM / 128, N_TOKENS / 128);     // (40, 16) = 640 CTAs, 2/SM
        mma_gemm_kernel<0><<<grid, 256, GEMM_SMEM>>>(tnorm, wqkv16, b_qkv, nullptr, nullptr,
                                                     QKV_DIM, HIDDEN);
    }

    // flash-style mma attention with sink (TQ=8, 3 CTAs/SM)
    {
        dim3 grid(N_TOKENS / TQ, N_KV);               // (256, 8) = 2048 CTAs
        attn_mma_kernel<<<grid, 128, ATTN_SMEM>>>(sink);
    }

    // join w_o convert, then O GEMM + bias + residual
    cudaStreamWaitEvent(0, ev_wo, 0);
    {
        dim3 grid((HIDDEN + 127) / 128, N_TOKENS / 128);  // (23, 16) = 368 CTAs, 2/SM
        mma_gemm_kernel<1><<<grid, 256, GEMM_SMEM>>>(attnb, wo16, b_o, x, out,
                                                     HIDDEN, Q_SZ);
    }
}